// round 15
// baseline (speedup 1.0000x reference)
#include <cuda_runtime.h>
#include <cuda_bf16.h>

// Problem constants (fixed by the dataset): B=256, T=512, K=128
#define Bn 256
#define Tn 512
#define Kn 128
#define NSOLO 40          // solo CTAs (longest batches), 1 batch each
#define NCTA  148         // 40 solo + 108 pair CTAs = all SMs

// Device scratch (no allocs allowed).
__device__ float g_partial[Bn];
__device__ int   g_perm[Bn];   // g_perm[rank] = batch index, ascending length
__device__ int   g_done;       // zero-init; last CTA resets to 0 each run

// ---- scheduler: grid=32 x 256 threads; warp w ranks batch 8*bx+w ----------
__global__ void crf_sched_kernel(const int* __restrict__ seq_lens)
{
    const int lane = threadIdx.x & 31;
    const int i    = blockIdx.x * 8 + (threadIdx.x >> 5);
    const int Li   = seq_lens[i];
    int r = 0;
    #pragma unroll
    for (int kk = 0; kk < 8; kk++) {
        int k  = lane + 32 * kk;
        int Lk = seq_lens[k];
        r += (Lk < Li) || (Lk == Li && k < i);   // unique ranks
    }
    #pragma unroll
    for (int o = 16; o; o >>= 1) r += __shfl_xor_sync(0xffffffffu, r, o);
    if (lane == 0) g_perm[r] = i;
}

__device__ __forceinline__ float frcp(float x) {
    float q; asm("rcp.approx.f32 %0, %1;" : "=f"(q) : "f"(x));
    return q;
}

// One scan step (measured ~350 cyc). Matvec warps 0-3: thread j owns the
// FULL column: 16 LDS.128 broadcast + 64 HFMA2 into 8 accumulators + pure
// bf16 tail with NO shuffle. cj comes from sh_ce (written by helper warps
// one phase earlier; parity-separated buffers -> race-free). Renorm (1-in-4)
// scales cj by rcp(beta[0]) -- read at phase start, hidden under FMA issue;
// S += logf(r) keeps the LSE shift identity exact. Helper warps 4-7: thread
// j publishes cj for the NEXT step = bf16x2(exp(logits[t+1, j])) and refills
// its raw prefetch register (stays 4+ steps / >1000 cyc ahead of use).
#define CRF_STEP(RDBUF_, WRBUF_, REN_, HREG_, NROW_) do {                    \
    if (isMat) {                                                             \
        unsigned ceu_ = sh_ce[RDBUF_][j];                                    \
        __nv_bfloat162 cj2_ = *(__nv_bfloat162*)&ceu_;                       \
        if (REN_) {                                                          \
            float rr_ = __bfloat162float(sh_beta[cur][0]);                   \
            S += __logf(rr_);                                                \
            cj2_ = __hmul2(cj2_, __float2bfloat162_rn(frcp(rr_)));           \
        }                                                                    \
        const uint4* ap_ = (const uint4*)sh_beta[cur];                       \
        __nv_bfloat162 z_; z_.x = __float2bfloat16(0.f); z_.y = z_.x;        \
        __nv_bfloat162 a0_=z_,a1_=z_,a2_=z_,a3_=z_,a4_=z_,a5_=z_,a6_=z_,a7_=z_; \
        _Pragma("unroll")                                                    \
        for (int L_ = 0; L_ < 16; L_ += 2) {                                 \
            uint4 v_ = ap_[L_];          /* LDS.128 pure broadcast */        \
            uint4 w_ = ap_[L_ + 1];                                          \
            a0_ = __hfma2(*(__nv_bfloat162*)&v_.x, eT2[4*L_+0], a0_);        \
            a1_ = __hfma2(*(__nv_bfloat162*)&v_.y, eT2[4*L_+1], a1_);        \
            a2_ = __hfma2(*(__nv_bfloat162*)&v_.z, eT2[4*L_+2], a2_);        \
            a3_ = __hfma2(*(__nv_bfloat162*)&v_.w, eT2[4*L_+3], a3_);        \
            a4_ = __hfma2(*(__nv_bfloat162*)&w_.x, eT2[4*L_+4], a4_);        \
            a5_ = __hfma2(*(__nv_bfloat162*)&w_.y, eT2[4*L_+5], a5_);        \
            a6_ = __hfma2(*(__nv_bfloat162*)&w_.z, eT2[4*L_+6], a6_);        \
            a7_ = __hfma2(*(__nv_bfloat162*)&w_.w, eT2[4*L_+7], a7_);        \
        }                                                                    \
        __nv_bfloat162 s_ =                                                  \
            __hadd2(__hadd2(__hadd2(a0_, a1_), __hadd2(a2_, a3_)),           \
                    __hadd2(__hadd2(a4_, a5_), __hadd2(a6_, a7_)));          \
        s_ = __hmul2(s_, cj2_);               /* mul before horizontal */    \
        __nv_bfloat162 sw_ = __lowhigh2highlow(s_);                          \
        __nv_bfloat162 tot_ = __hadd2(s_, sw_);                              \
        sh_beta[cur ^ 1][j] = tot_.x;                                        \
    } else {                                                                 \
        __nv_bfloat162 ce_ = __float2bfloat162_rn(__expf(HREG_));            \
        sh_ce[WRBUF_][j] = *(unsigned*)&ce_;                                 \
        HREG_ = NROW_;                        /* refill raw prefetch */      \
    }                                                                        \
    __syncthreads();                          /* the ONLY barrier/step */    \
    cur ^= 1;                                                                \
} while (0)

// Hybrid schedule over 148 SMs, ONE engine everywhere:
//   CTAs 0..39   : 1 batch,  perm[255-c]              (the 40 longest)
//   CTAs 40..147 : 2 batches perm[k], perm[215-k]     (k=c-40; sums ~434)
// Makespan = 512 steps x engine rate (~350 cyc) — the single longest batch.
__global__ __launch_bounds__(256, 1) void crf_forward_kernel(
    const float* __restrict__ logits,   // [B, T, K]
    const int*   __restrict__ labels,   // [B, T]
    const int*   __restrict__ seq_lens, // [B]
    const float* __restrict__ trans,    // [K, K] trans[i*K + j]
    float* __restrict__ out)
{
    __shared__ __align__(16) __nv_bfloat16 sh_beta[2][Kn];
    __shared__ unsigned sh_ce[2][Kn];    // packed bf16x2 cj, double-buffered
    __shared__ float sh_wred[8];
    __shared__ int   sh_last;

    const int c     = blockIdx.x;         // 0..147
    const int tau   = threadIdx.x;        // 0..255
    const bool isMat = (tau < Kn);        // warps 0-3
    const int j     = isMat ? tau : (tau - Kn);   // column 0..127
    const int lane  = tau & 31;
    const int warp  = tau >> 5;

    const bool solo = (c < NSOLO);
    const int  nb   = solo ? 1 : 2;
    const int  r0   = solo ? ((Bn - 1) - c) : (c - NSOLO);
    const int  r1   = 215 - (c - NSOLO);

    // expT[:, j] as 64 bf16x2 over row-pairs (matvec threads only)
    __nv_bfloat162 eT2[64];
    if (isMat) {
        #pragma unroll
        for (int k = 0; k < 64; k++) {
            float e0 = __expf(trans[(2 * k)     * Kn + j]);   // coalesced
            float e1 = __expf(trans[(2 * k + 1) * Kn + j]);
            eT2[k] = __floats2bfloat162_rn(e0, e1);
        }
    }

    for (int p = 0; p < nb; p++) {
        const int b = g_perm[p ? r1 : r0];
        const int    Tlen = seq_lens[b];                  // 1..512
        const float* lg   = logits + (size_t)b * Tn * Kn;
        const int*   lb   = labels + b * Tn;

        // ---------- gold-path score: unary + pairwise (fp32 exact) --------
        float sc = 0.f;
        for (int t = tau; t < Tlen; t += 256) {
            int y = lb[t];
            sc += lg[t * Kn + y];
            if (t >= 1) sc += trans[lb[t - 1] * Kn + y];
        }
        #pragma unroll
        for (int o = 16; o; o >>= 1) sc += __shfl_xor_sync(0xffffffffu, sc, o);
        if (lane == 0) sh_wred[warp] = sc;

        #define ROW(tt) lg[(((tt) < Tn) ? (tt) : (Tn - 1)) * Kn + j]
        // Prologue: matvec writes beta_0; helpers write cj for step 1 into
        // buf 1 and preload raw rows 2..5 (cj for steps 2..5 in phases 1..4).
        float h0 = 0.f, h1 = 0.f, h2 = 0.f, h3 = 0.f;
        if (isMat) {
            sh_beta[0][j] = __float2bfloat16(__expf(lg[j]));
        } else {
            __nv_bfloat162 ce0 = __float2bfloat162_rn(__expf(ROW(1)));
            sh_ce[1][j] = *(unsigned*)&ce0;
            h0 = ROW(2); h1 = ROW(3); h2 = ROW(4); h3 = ROW(5);
        }
        __syncthreads();
        float score = 0.f;
        #pragma unroll
        for (int w = 0; w < 8; w++) score += sh_wred[w];

        // ---------- forward recursion, 4x unrolled, renorm 1-in-4 ---------
        // t stays ≡ 1 (mod 4): slots read ce buf 1,0,1,0 / write 0,1,0,1.
        float S   = 0.f;
        int   cur = 0;
        int   t   = 1;
        while (t + 3 < Tlen) {
            CRF_STEP(1, 0, true,  h0, ROW(t + 6));   // step t   (renorm)
            CRF_STEP(0, 1, false, h1, ROW(t + 7));   // step t+1
            CRF_STEP(1, 0, false, h2, ROW(t + 8));   // step t+2
            CRF_STEP(0, 1, false, h3, ROW(t + 9));   // step t+3
            t += 4;
        }
        // remainder <= 3 steps; helpers' h0..h2 hold rows t+1..t+3
        if (t     < Tlen) CRF_STEP(1, 0, true,  h0, 0.f);
        if (t + 1 < Tlen) CRF_STEP(0, 1, false, h1, 0.f);
        if (t + 2 < Tlen) CRF_STEP(1, 0, false, h2, 0.f);
        #undef ROW

        // ---------- log_z = S + log(sum_j beta_j) (fp32 reduce) -----------
        float v = isMat ? __bfloat162float(sh_beta[cur][j]) : 0.f;
        #pragma unroll
        for (int o = 16; o; o >>= 1) v += __shfl_xor_sync(0xffffffffu, v, o);
        __syncthreads();                     // old sh_wred reads done
        if (lane == 0) sh_wred[warp] = v;
        __syncthreads();

        if (tau == 0) {
            float stot = (sh_wred[0] + sh_wred[1]) + (sh_wred[2] + sh_wred[3]);
            g_partial[b] = S + __logf(stot) - score;   // per-batch NLL
        }
        __syncthreads();                     // smem safe for next batch
    }

    // ---------- fused final reduction: last CTA sums deterministically ----
    if (tau == 0) {
        __threadfence();
        int d = atomicAdd(&g_done, 1);
        sh_last = (d == (NCTA - 1));
    }
    __syncthreads();
    if (sh_last) {
        __threadfence();                 // see all CTAs' g_partial writes
        float w = g_partial[tau];        // fixed-tree: deterministic
        #pragma unroll
        for (int o = 16; o; o >>= 1) w += __shfl_xor_sync(0xffffffffu, w, o);
        if (lane == 0) sh_wred[warp] = w;
        __syncthreads();
        if (tau == 0) {
            float s = ((sh_wred[0] + sh_wred[1]) + (sh_wred[2] + sh_wred[3]))
                    + ((sh_wred[4] + sh_wred[5]) + (sh_wred[6] + sh_wred[7]));
            out[0]  = s;
            g_done  = 0;                 // reset for next graph replay
        }
    }
}

extern "C" void kernel_launch(void* const* d_in, const int* in_sizes, int n_in,
                              void* d_out, int out_size)
{
    const float* logits   = (const float*)d_in[0];
    const int*   labels   = (const int*)  d_in[1];
    const int*   seq_lens = (const int*)  d_in[2];
    const float* trans    = (const float*)d_in[3];
    float*       out      = (float*)d_out;

    crf_sched_kernel<<<32, 256>>>(seq_lens);
    crf_forward_kernel<<<NCTA, 256>>>(logits, labels, seq_lens, trans, out);
}

// round 16
// speedup vs baseline: 1.1506x; 1.1506x over previous
#include <cuda_runtime.h>
#include <cuda_bf16.h>

// Problem constants (fixed by the dataset): B=256, T=512, K=128
#define Bn 256
#define Tn 512
#define Kn 128
#define NSOLO 40          // solo CTAs (longest batches), 1 batch each
#define NCTA  148         // 40 solo + 108 pair CTAs = all SMs

// Device scratch (no allocs allowed).
__device__ float g_partial[Bn];
__device__ int   g_perm[Bn];   // g_perm[rank] = batch index, ascending length
__device__ int   g_done;       // zero-init; last CTA resets to 0 each run

// ---- scheduler: grid=32 x 256 threads; warp w ranks batch 8*bx+w ----------
__global__ void crf_sched_kernel(const int* __restrict__ seq_lens)
{
    const int lane = threadIdx.x & 31;
    const int i    = blockIdx.x * 8 + (threadIdx.x >> 5);
    const int Li   = seq_lens[i];
    int r = 0;
    #pragma unroll
    for (int kk = 0; kk < 8; kk++) {
        int k  = lane + 32 * kk;
        int Lk = seq_lens[k];
        r += (Lk < Li) || (Lk == Li && k < i);   // unique ranks
    }
    #pragma unroll
    for (int o = 16; o; o >>= 1) r += __shfl_xor_sync(0xffffffffu, r, o);
    if (lane == 0) g_perm[r] = i;
}

__device__ __forceinline__ float frcp(float x) {
    float q; asm("rcp.approx.f32 %0, %1;" : "=f"(q) : "f"(x));
    return q;
}

// Fused fwd+bwd step. Matvec warps 0-3: thread j owns expT column j (fwd) and
// expT row j (bwd): 32 LDS.128 + 128 HFMA2 + two no-shuffle bf16 tails. cj
// streams come from sh_ceF/sh_ceB written by helper warps one step earlier
// (parity buffers, race-free under the per-step barrier). Renorm (1-in-4)
// rescales each chain by rcp of its element 0; S accumulates logf -> exact
// LSE shift identity per chain. LASTF_ replaces the fwd multiplier with 1
// (the q_m = M^T beta_{m-1} step of the split identity).
#define FSTEP(RD_, WR_, REN_, LASTF_, HF_, HB_, NRF_, NRB_) do {             \
    if (isMat) {                                                             \
        unsigned uF_ = sh_ceF[RD_][j];                                       \
        unsigned uB_ = sh_ceB[RD_][j];                                       \
        __nv_bfloat162 cjF_ = (LASTF_) ? one2 : *(__nv_bfloat162*)&uF_;      \
        __nv_bfloat162 cjB_ = *(__nv_bfloat162*)&uB_;                        \
        if (REN_) {                                                          \
            float rF_ = __bfloat162float(shF[curF][0]);                      \
            float rB_ = __bfloat162float(shB[curB][0]);                      \
            Sf += __logf(rF_); Sb += __logf(rB_);                            \
            cjF_ = __hmul2(cjF_, __float2bfloat162_rn(frcp(rF_)));           \
            cjB_ = __hmul2(cjB_, __float2bfloat162_rn(frcp(rB_)));           \
        }                                                                    \
        const uint4* apF_ = (const uint4*)shF[curF];                         \
        const uint4* apB_ = (const uint4*)shB[curB];                         \
        __nv_bfloat162 f0_=zero2,f1_=zero2,f2_=zero2,f3_=zero2;              \
        __nv_bfloat162 b0_=zero2,b1_=zero2,b2_=zero2,b3_=zero2;              \
        _Pragma("unroll")                                                    \
        for (int L_ = 0; L_ < 16; L_++) {                                    \
            uint4 vF_ = apF_[L_];            /* LDS.128 broadcast */         \
            uint4 vB_ = apB_[L_];                                            \
            f0_ = __hfma2(*(__nv_bfloat162*)&vF_.x, eTf[4*L_+0], f0_);       \
            f1_ = __hfma2(*(__nv_bfloat162*)&vF_.y, eTf[4*L_+1], f1_);       \
            f2_ = __hfma2(*(__nv_bfloat162*)&vF_.z, eTf[4*L_+2], f2_);       \
            f3_ = __hfma2(*(__nv_bfloat162*)&vF_.w, eTf[4*L_+3], f3_);       \
            b0_ = __hfma2(*(__nv_bfloat162*)&vB_.x, eTb[4*L_+0], b0_);       \
            b1_ = __hfma2(*(__nv_bfloat162*)&vB_.y, eTb[4*L_+1], b1_);       \
            b2_ = __hfma2(*(__nv_bfloat162*)&vB_.z, eTb[4*L_+2], b2_);       \
            b3_ = __hfma2(*(__nv_bfloat162*)&vB_.w, eTb[4*L_+3], b3_);       \
        }                                                                    \
        __nv_bfloat162 sF_ = __hadd2(__hadd2(f0_, f1_), __hadd2(f2_, f3_));  \
        sF_ = __hmul2(sF_, cjF_);                                            \
        __nv_bfloat162 tF_ = __hadd2(sF_, __lowhigh2highlow(sF_));           \
        shF[curF ^ 1][j] = tF_.x;                                            \
        __nv_bfloat162 sB_ = __hadd2(__hadd2(b0_, b1_), __hadd2(b2_, b3_));  \
        sB_ = __hmul2(sB_, cjB_);                                            \
        __nv_bfloat162 tB_ = __hadd2(sB_, __lowhigh2highlow(sB_));           \
        shB[curB ^ 1][j] = tB_.x;                                            \
    } else {                                                                 \
        __nv_bfloat162 eF_ = __float2bfloat162_rn(__expf(HF_));              \
        sh_ceF[WR_][j] = *(unsigned*)&eF_;                                   \
        __nv_bfloat162 eB_ = __float2bfloat162_rn(__expf(HB_));              \
        sh_ceB[WR_][j] = *(unsigned*)&eB_;                                   \
        HF_ = NRF_; HB_ = NRB_;              /* refill raw prefetch */       \
    }                                                                        \
    __syncthreads();                         /* the ONLY barrier/step */     \
    curF ^= 1; curB ^= 1;                                                    \
} while (0)

// Extra forward-only step when (Tlen-1) is odd: cj = 1, no renorm.
#define FWD1() do {                                                          \
    if (isMat) {                                                             \
        const uint4* apF_ = (const uint4*)shF[curF];                         \
        __nv_bfloat162 f0_=zero2,f1_=zero2,f2_=zero2,f3_=zero2;              \
        _Pragma("unroll")                                                    \
        for (int L_ = 0; L_ < 16; L_++) {                                    \
            uint4 vF_ = apF_[L_];                                            \
            f0_ = __hfma2(*(__nv_bfloat162*)&vF_.x, eTf[4*L_+0], f0_);       \
            f1_ = __hfma2(*(__nv_bfloat162*)&vF_.y, eTf[4*L_+1], f1_);       \
            f2_ = __hfma2(*(__nv_bfloat162*)&vF_.z, eTf[4*L_+2], f2_);       \
            f3_ = __hfma2(*(__nv_bfloat162*)&vF_.w, eTf[4*L_+3], f3_);       \
        }                                                                    \
        __nv_bfloat162 sF_ = __hadd2(__hadd2(f0_, f1_), __hadd2(f2_, f3_));  \
        __nv_bfloat162 tF_ = __hadd2(sF_, __lowhigh2highlow(sF_));           \
        shF[curF ^ 1][j] = tF_.x;                                            \
    }                                                                        \
    __syncthreads();                                                         \
    curF ^= 1;                                                               \
} while (0)

// Hybrid schedule over 148 SMs; every batch is fwd/bwd split in one CTA:
//   CTAs 0..39   : 1 batch,  perm[255-c]           -> ~(L/2) fused steps
//   CTAs 40..147 : 2 batches perm[k], perm[215-k]  -> ~(L1+L2)/2 fused steps
// Makespan = 256 fused steps for the T=512 batch (was 511 sequential steps).
__global__ __launch_bounds__(256, 1) void crf_forward_kernel(
    const float* __restrict__ logits,   // [B, T, K]
    const int*   __restrict__ labels,   // [B, T]
    const int*   __restrict__ seq_lens, // [B]
    const float* __restrict__ trans,    // [K, K] trans[i*K + j]
    float* __restrict__ out)
{
    __shared__ __align__(16) __nv_bfloat16 shF[2][Kn];
    __shared__ __align__(16) __nv_bfloat16 shB[2][Kn];
    __shared__ unsigned sh_ceF[2][Kn];   // fwd cj stream (bf16x2 packed)
    __shared__ unsigned sh_ceB[2][Kn];   // bwd cj stream
    __shared__ float sh_wred[8];
    __shared__ int   sh_last;

    const int c     = blockIdx.x;         // 0..147
    const int tau   = threadIdx.x;        // 0..255
    const bool isMat = (tau < Kn);        // warps 0-3
    const int j     = isMat ? tau : (tau - Kn);   // column/row 0..127
    const int lane  = tau & 31;
    const int warp  = tau >> 5;

    const bool solo = (c < NSOLO);
    const int  nb   = solo ? 1 : 2;
    const int  r0   = solo ? ((Bn - 1) - c) : (c - NSOLO);
    const int  r1   = 215 - (c - NSOLO);

    const __nv_bfloat162 zero2 = __float2bfloat162_rn(0.f);
    const __nv_bfloat162 one2  = __float2bfloat162_rn(1.f);

    // eTf[k] = expT column j (rows 2k,2k+1); eTb[k] = expT row j (cols 2k,2k+1)
    __nv_bfloat162 eTf[64], eTb[64];
    if (isMat) {
        #pragma unroll
        for (int k = 0; k < 64; k++) {
            float e0 = __expf(trans[(2 * k)     * Kn + j]);   // coalesced
            float e1 = __expf(trans[(2 * k + 1) * Kn + j]);
            eTf[k] = __floats2bfloat162_rn(e0, e1);
            float r0_ = __expf(trans[j * Kn + 2 * k]);        // row stream
            float r1_ = __expf(trans[j * Kn + 2 * k + 1]);
            eTb[k] = __floats2bfloat162_rn(r0_, r1_);
        }
    }

    for (int p = 0; p < nb; p++) {
        const int b = g_perm[p ? r1 : r0];
        const int    Tlen = seq_lens[b];                  // 1..512
        const float* lg   = logits + (size_t)b * Tn * Kn;
        const int*   lb   = labels + b * Tn;

        // ---------- gold-path score: unary + pairwise (fp32 exact) --------
        float sc = 0.f;
        for (int t = tau; t < Tlen; t += 256) {
            int y = lb[t];
            sc += lg[t * Kn + y];
            if (t >= 1) sc += trans[lb[t - 1] * Kn + y];
        }
        #pragma unroll
        for (int o = 16; o; o >>= 1) sc += __shfl_xor_sync(0xffffffffu, sc, o);
        if (lane == 0) sh_wred[warp] = sc;

        #define ROWF(tt) lg[(((tt) < Tn) ? (tt) : (Tn - 1)) * Kn + j]
        #define ROWB(tt) lg[(((tt) > 0) ? (tt) : 0) * Kn + j]
        // Prologue. Matvec: seeds shF = c_0, shB = c_{T-1} (or 1 if T==1).
        // Helpers: cj for fused step 0 into buf 1 (fwd row 1, bwd row T-2)
        // and raw prefetch of the next 4 rows of each stream.
        float hF0 = 0.f, hF1 = 0.f, hF2 = 0.f, hF3 = 0.f;
        float hB0 = 0.f, hB1 = 0.f, hB2 = 0.f, hB3 = 0.f;
        if (isMat) {
            shF[0][j] = __float2bfloat16(__expf(lg[j]));
            shB[0][j] = (Tlen == 1) ? __float2bfloat16(1.f)
                        : __float2bfloat16(__expf(lg[(Tlen - 1) * Kn + j]));
        } else {
            __nv_bfloat162 cf = __float2bfloat162_rn(__expf(ROWF(1)));
            sh_ceF[1][j] = *(unsigned*)&cf;
            __nv_bfloat162 cb = __float2bfloat162_rn(__expf(ROWB(Tlen - 2)));
            sh_ceB[1][j] = *(unsigned*)&cb;
            hF0 = ROWF(2); hF1 = ROWF(3); hF2 = ROWF(4); hF3 = ROWF(5);
            hB0 = ROWB(Tlen - 3); hB1 = ROWB(Tlen - 4);
            hB2 = ROWB(Tlen - 5); hB3 = ROWB(Tlen - 6);
        }
        __syncthreads();
        float score = 0.f;
        #pragma unroll
        for (int w = 0; w < 8; w++) score += sh_wred[w];

        // ---------- fused fwd+bwd recursion ----------
        const int nsteps = Tlen - 1;
        const int F      = nsteps >> 1;       // fused steps
        const int odd    = nsteps & 1;        // extra fwd-only (cj=1) step
        float Sf = 0.f, Sb = 0.f;
        int curF = 0, curB = 0;
        int f = 0;
        while (f + 3 < F) {
            FSTEP(1, 0, true,  false, hF0, hB0, ROWF(f + 6),  ROWB(Tlen - 7 - f));
            FSTEP(0, 1, false, false, hF1, hB1, ROWF(f + 7),  ROWB(Tlen - 8 - f));
            FSTEP(1, 0, false, false, hF2, hB2, ROWF(f + 8),  ROWB(Tlen - 9 - f));
            FSTEP(0, 1, false, ((f + 4 == F) && !odd),
                               hF3, hB3, ROWF(f + 9),  ROWB(Tlen - 10 - f));
            f += 4;
        }
        // remainder fused steps (<=3); helper regs hold the needed rows
        if (f     < F) FSTEP(1, 0, true,  ((f + 1 == F) && !odd), hF0, hB0, 0.f, 0.f);
        if (f + 1 < F) FSTEP(0, 1, false, ((f + 2 == F) && !odd), hF1, hB1, 0.f, 0.f);
        if (f + 2 < F) FSTEP(1, 0, false, ((f + 3 == F) && !odd), hF2, hB2, 0.f, 0.f);
        if (odd) FWD1();                      // q_m step when nsteps is odd
        #undef ROWF
        #undef ROWB

        // ---------- log_z = Sf + Sb + log(dot(shF, shB)) ------------------
        float v = isMat ? (__bfloat162float(shF[curF][j]) *
                           __bfloat162float(shB[curB][j])) : 0.f;
        #pragma unroll
        for (int o = 16; o; o >>= 1) v += __shfl_xor_sync(0xffffffffu, v, o);
        __syncthreads();                     // old sh_wred reads done
        if (lane == 0) sh_wred[warp] = v;
        __syncthreads();

        if (tau == 0) {
            float dot = (sh_wred[0] + sh_wred[1]) + (sh_wred[2] + sh_wred[3]);
            g_partial[b] = Sf + Sb + __logf(dot) - score;   // per-batch NLL
        }
        __syncthreads();                     // smem safe for next batch
    }

    // ---------- fused final reduction: last CTA sums deterministically ----
    if (tau == 0) {
        __threadfence();
        int d = atomicAdd(&g_done, 1);
        sh_last = (d == (NCTA - 1));
    }
    __syncthreads();
    if (sh_last) {
        __threadfence();                 // see all CTAs' g_partial writes
        float w = g_partial[tau];        // fixed-tree: deterministic
        #pragma unroll
        for (int o = 16; o; o >>= 1) w += __shfl_xor_sync(0xffffffffu, w, o);
        if (lane == 0) sh_wred[warp] = w;
        __syncthreads();
        if (tau == 0) {
            float s = ((sh_wred[0] + sh_wred[1]) + (sh_wred[2] + sh_wred[3]))
                    + ((sh_wred[4] + sh_wred[5]) + (sh_wred[6] + sh_wred[7]));
            out[0]  = s;
            g_done  = 0;                 // reset for next graph replay
        }
    }
}

extern "C" void kernel_launch(void* const* d_in, const int* in_sizes, int n_in,
                              void* d_out, int out_size)
{
    const float* logits   = (const float*)d_in[0];
    const int*   labels   = (const int*)  d_in[1];
    const int*   seq_lens = (const int*)  d_in[2];
    const float* trans    = (const float*)d_in[3];
    float*       out      = (float*)d_out;

    crf_sched_kernel<<<32, 256>>>(seq_lens);
    crf_forward_kernel<<<NCTA, 256>>>(logits, labels, seq_lens, trans, out);
}